// round 7
// baseline (speedup 1.0000x reference)
#include <cuda_runtime.h>

#define N_NODES 10000
#define N_EDGES 320000
#define QUADS (N_EDGES / 4)
#define NB 148
#define NT 1024
#define NTHR (NB * NT)
#define BM_WORDS 320
#define DC3 209   // 48 dot blocks in P3
#define DC4 313   // 32 dot blocks in P4
#define DC5 68    // 148 dot blocks in P5

// Packed probe-vector storage. INVARIANT: all __device__ scratch is ZERO at
// kernel entry and restored to ZERO before exit (module load guarantees the
// first call; each call re-zeroes after last use).
__device__ float2 g_CL1[N_NODES];   // {R1, R2}
__device__ float4 g_CL2[N_NODES];   // {R3, R5, R4, R6}
__device__ float4 g_CL3a[N_NODES];  // {R7, R10, R11, pad}
__device__ float4 g_CL3b[N_NODES];  // {R8, R9, R12, pad}
__device__ float4 g_CL4[N_NODES];   // {R13, R15, R14, R16}
__device__ unsigned g_bm1[BM_WORDS];
__device__ unsigned g_bm2[BM_WORDS];
__device__ float g_D[17][4][64];
__device__ float g_T[5][4][128];
__device__ float g_sig[5];
__device__ int g_count;             // returns to 0 at each barrier
__device__ volatile int g_gen;      // monotonic; equality-compare only

__constant__ int c_VEC_ID[5][5] = {
    {0, 1, 3, 2, 6},
    {1, 3, 7, 4, 9},
    {3, 7, 13, 8, 14},
    {2, 5, 10, 6, 12},
    {6, 11, 15, 12, 16}};
__constant__ int c_VID3[6] = {1, 2, 3, 5, 4, 6};     // CL1.xy, CL2.xyzw vids
__constant__ int c_VID4[6] = {7, 10, 11, 8, 9, 12};  // CL3a.xyz, CL3b.xyz
__constant__ int c_VID5[4] = {13, 15, 14, 16};       // CL4.xyzw

__device__ __forceinline__ void red2(float* p, float a, float b) {
    asm volatile("red.global.add.v2.f32 [%0], {%1,%2};" :: "l"(p), "f"(a), "f"(b) : "memory");
}
__device__ __forceinline__ void red4(float* p, float a, float b, float c, float d) {
    asm volatile("red.global.add.v4.f32 [%0], {%1,%2,%3,%4};"
                 :: "l"(p), "f"(a), "f"(b), "f"(c), "f"(d) : "memory");
}
__device__ __forceinline__ float ldcg1(const float* p) {
    float r; asm volatile("ld.global.cg.f32 %0,[%1];" : "=f"(r) : "l"(p)); return r;
}
__device__ __forceinline__ unsigned ldcg1u(const unsigned* p) {
    unsigned r; asm volatile("ld.global.cg.u32 %0,[%1];" : "=r"(r) : "l"(p)); return r;
}
__device__ __forceinline__ float2 ldcg2(const float2* p) {
    float2 r; asm volatile("ld.global.cg.v2.f32 {%0,%1},[%2];"
                           : "=f"(r.x), "=f"(r.y) : "l"(p)); return r;
}
__device__ __forceinline__ float4 ldcg4(const float4* p) {
    float4 r; asm volatile("ld.global.cg.v4.f32 {%0,%1,%2,%3},[%4];"
                           : "=f"(r.x), "=f"(r.y), "=f"(r.z), "=f"(r.w) : "l"(p)); return r;
}

__device__ __forceinline__ void barrier_arrive(int target) {
    __syncthreads();
    if (threadIdx.x == 0) {
        __threadfence();
        int gen = g_gen;
        if (atomicAdd(&g_count, 1) == target - 1) {
            g_count = 0;
            __threadfence();
            g_gen = gen + 1;
        }
    }
}
__device__ __forceinline__ void barrier_wait(int target) {
    __syncthreads();
    if (threadIdx.x == 0) {
        __threadfence();
        int gen = g_gen;
        if (atomicAdd(&g_count, 1) == target - 1) {
            g_count = 0;
            __threadfence();
            g_gen = gen + 1;
        } else {
            while (g_gen == gen) __nanosleep(64);
        }
    }
    __syncthreads();
}

// Dot over one staged node-chunk: thread=(f,b,sub); NS slot accumulators.
template <int NS, int DC>
__device__ __forceinline__ void dot_chunk(const float* __restrict__ x, int n0, int lim,
                                          const float* __restrict__ Rs, const int* vids) {
    int tid = threadIdx.x;
    int f = tid & 63, b = (tid >> 6) & 3, sub = tid >> 8;
    float acc[NS];
#pragma unroll
    for (int s = 0; s < NS; s++) acc[s] = 0.f;
    const float* xb = x + ((size_t)b * N_NODES + n0) * 64 + f;
    for (int nn = sub; nn < lim; nn += 4) {
        float xv = __ldg(xb + (size_t)nn * 64);
#pragma unroll
        for (int s = 0; s < NS; s++) acc[s] += Rs[s * DC + nn] * xv;
    }
#pragma unroll
    for (int s = 0; s < NS; s++) atomicAdd(&g_D[vids[s]][b][f], acc[s]);
}

__global__ void __launch_bounds__(NT, 1)
fused_kernel(const int* __restrict__ eidx, const float* __restrict__ evals,
             const float* __restrict__ x,
             const float* __restrict__ W1, const float* __restrict__ b1,
             const float* __restrict__ W2, const float* __restrict__ b2,
             float* __restrict__ out) {
    __shared__ __align__(16) float pool[1920];  // Rs (dot) / part (epilogue)
    __shared__ unsigned sbm[BM_WORDS];
    float4 (*part)[32] = reinterpret_cast<float4(*)[32]>(pool);

    const int tid = threadIdx.x;
    const int blk = blockIdx.x;
    const int gtid = blk * NT + tid;
    const float4 z4 = make_float4(0.f, 0.f, 0.f, 0.f);

    // ---- P1: lvl1 (parent = e_0) + build bm1 ----
    for (int q = gtid; q < 2 * QUADS; q += NTHR) {
        int g = q >= QUADS;
        int j = q - g * QUADS;
        const int* eb = eidx + (size_t)g * 2 * N_EDGES;
        int4 r = __ldg((const int4*)eb + j);
        if (r.x == 0 || r.y == 0 || r.z == 0 || r.w == 0) {
            const int ri[4] = {r.x, r.y, r.z, r.w};
            float* base = (float*)g_CL1 + g;
#pragma unroll
            for (int i = 0; i < 4; i++)
                if (ri[i] == 0) {
                    int c = __ldg(eb + N_EDGES + j * 4 + i);
                    float v = __ldg(evals + (size_t)g * N_EDGES + j * 4 + i);
                    atomicAdd(base + c * 2, v);
                    atomicOr(&g_bm1[c >> 5], 1u << (c & 31));
                }
        }
    }
    barrier_wait(NB);

    // ---- P2: lvl2 (bm1-filtered) + build bm2 ----
    if (tid < BM_WORDS) sbm[tid] = ldcg1u(&g_bm1[tid]);
    __syncthreads();
    for (int q = gtid; q < 2 * QUADS; q += NTHR) {
        int g = q >= QUADS;
        int j = q - g * QUADS;
        const int* eb = eidx + (size_t)g * 2 * N_EDGES;
        int4 r = __ldg((const int4*)eb + j);
        const int ri[4] = {r.x, r.y, r.z, r.w};
        unsigned any = 0;
#pragma unroll
        for (int i = 0; i < 4; i++)
            any |= (sbm[ri[i] >> 5] >> (ri[i] & 31)) & 1u ? (1u << i) : 0u;
        if (!any) continue;
        float* base = (float*)g_CL2 + 2 * g;
#pragma unroll
        for (int i = 0; i < 4; i++)
            if (any & (1u << i)) {
                float2 qv = ldcg2(g_CL1 + ri[i]);
                if ((qv.x != 0.f) | (qv.y != 0.f)) {
                    int c = __ldg(eb + N_EDGES + j * 4 + i);
                    float v = __ldg(evals + (size_t)g * N_EDGES + j * 4 + i);
                    red2(base + c * 4, v * qv.x, v * qv.y);
                    atomicOr(&g_bm2[c >> 5], 1u << (c & 31));
                }
            }
    }
    barrier_wait(NB);

    // ---- P3: blocks 0..99 lvl3 scan; blocks 100..147 dot(CL1,CL2) + sigma ----
    if (blk < 100) {
        if (tid < BM_WORDS) sbm[tid] = ldcg1u(&g_bm2[tid]);
        __syncthreads();
        for (int q = blk * NT + tid; q < 2 * QUADS; q += 100 * NT) {
            int g = q >= QUADS;
            int j = q - g * QUADS;
            const int* eb = eidx + (size_t)g * 2 * N_EDGES;
            int4 r = __ldg((const int4*)eb + j);
            const int ri[4] = {r.x, r.y, r.z, r.w};
            unsigned any = 0;
#pragma unroll
            for (int i = 0; i < 4; i++)
                any |= (sbm[ri[i] >> 5] >> (ri[i] & 31)) & 1u ? (1u << i) : 0u;
            if (!any) continue;
            float4* dst = g ? g_CL3b : g_CL3a;
#pragma unroll
            for (int i = 0; i < 4; i++)
                if (any & (1u << i)) {
                    float4 qv = ldcg4(g_CL2 + ri[i]);
                    float p0 = qv.x;
                    float p1 = g ? qv.z : qv.y;
                    float p2 = qv.w;
                    if ((p0 != 0.f) | (p1 != 0.f) | (p2 != 0.f)) {
                        int c = __ldg(eb + N_EDGES + j * 4 + i);
                        float v = __ldg(evals + (size_t)g * N_EDGES + j * 4 + i);
                        red4((float*)&dst[c], v * p0, v * p1, v * p2, 0.f);
                    }
                }
        }
    } else {
        int t = blk - 100;
        int n0 = t * DC3;
        int lim = min(DC3, N_NODES - n0);
        for (int i = tid; i < lim; i += NT) {
            float2 a = ldcg2(g_CL1 + n0 + i);
            float4 c2 = ldcg4(g_CL2 + n0 + i);
            pool[0 * DC3 + i] = a.x;  pool[1 * DC3 + i] = a.y;
            pool[2 * DC3 + i] = c2.x; pool[3 * DC3 + i] = c2.y;
            pool[4 * DC3 + i] = c2.z; pool[5 * DC3 + i] = c2.w;
        }
        __syncthreads();
        if (tid < 128) {  // sigma: sig[1..4] = sums of slots {0,2,1,5}
            const int slots[4] = {0, 2, 1, 5};
            int vi = tid >> 5, lane = tid & 31;
            float s = 0.f;
            for (int n = lane; n < lim; n += 32) s += pool[slots[vi] * DC3 + n];
#pragma unroll
            for (int off = 16; off; off >>= 1) s += __shfl_down_sync(0xffffffffu, s, off);
            if (lane == 0) atomicAdd(&g_sig[vi + 1], s);
        }
        dot_chunk<6, DC3>(x, n0, lim, pool, c_VID3);
    }
    barrier_wait(NB);

    // ---- P4: blocks 0..111 lvl4 scan; 112..143 dot(CL3); 144..147 zero CL1/CL2/bm ----
    if (blk < 112) {
        for (int q = blk * NT + tid; q < 2 * QUADS; q += 112 * NT) {
            int g = q >= QUADS;
            int j = q - g * QUADS;
            const int* eb = eidx + (size_t)g * 2 * N_EDGES;
            const float4* src = g ? g_CL3b : g_CL3a;
            int4 r = __ldg((const int4*)eb + j);
            int4 c = __ldg((const int4*)(eb + N_EDGES) + j);
            float4 v = __ldg((const float4*)(evals + (size_t)g * N_EDGES) + j);
            float* base = (float*)g_CL4 + 2 * g;
            {
                float4 q0 = ldcg4(src + r.x), q1 = ldcg4(src + r.y);
                if ((q0.x != 0.f) | (q0.z != 0.f)) red2(base + c.x * 4, v.x * q0.x, v.x * q0.z);
                if ((q1.x != 0.f) | (q1.z != 0.f)) red2(base + c.y * 4, v.y * q1.x, v.y * q1.z);
            }
            {
                float4 q2 = ldcg4(src + r.z), q3 = ldcg4(src + r.w);
                if ((q2.x != 0.f) | (q2.z != 0.f)) red2(base + c.z * 4, v.z * q2.x, v.z * q2.z);
                if ((q3.x != 0.f) | (q3.z != 0.f)) red2(base + c.w * 4, v.w * q3.x, v.w * q3.z);
            }
        }
    } else if (blk < 144) {
        int t = blk - 112;
        int n0 = t * DC4;
        int lim = min(DC4, N_NODES - n0);
        for (int i = tid; i < lim; i += NT) {
            float4 a = ldcg4(g_CL3a + n0 + i);
            float4 b_ = ldcg4(g_CL3b + n0 + i);
            pool[0 * DC4 + i] = a.x;  pool[1 * DC4 + i] = a.y;  pool[2 * DC4 + i] = a.z;
            pool[3 * DC4 + i] = b_.x; pool[4 * DC4 + i] = b_.y; pool[5 * DC4 + i] = b_.z;
        }
        __syncthreads();
        dot_chunk<6, DC4>(x, n0, lim, pool, c_VID4);
    } else {
        int t = blk - 144;
        for (int i = t * NT + tid; i < N_NODES; i += 4 * NT) {
            g_CL1[i] = make_float2(0.f, 0.f);
            g_CL2[i] = z4;
        }
        int gi = t * NT + tid;
        if (gi < BM_WORDS) { g_bm1[gi] = 0u; g_bm2[gi] = 0u; }
    }
    barrier_wait(NB);

    // ---- P5: all blocks dot(CL4) + zero CL3/CL4 chunk ----
    {
        int n0 = blk * DC5;
        int lim = min(DC5, N_NODES - n0);
        for (int i = tid; i < lim; i += NT) {
            int gn = n0 + i;
            float4 a = ldcg4(g_CL4 + gn);
            pool[0 * DC5 + i] = a.x; pool[1 * DC5 + i] = a.y;
            pool[2 * DC5 + i] = a.z; pool[3 * DC5 + i] = a.w;
            g_CL4[gn] = z4;
            g_CL3a[gn] = z4;
            g_CL3b[gn] = z4;
        }
        __syncthreads();
        dot_chunk<4, DC5>(x, n0, lim, pool, c_VID5);
    }
    if (blk >= 124) { barrier_arrive(NB); return; }
    barrier_wait(NB);

    // ---- P6a: blocks 0..119 T partials; 120..123 init out = b2 ----
    {
        int lane = tid & 31, w = tid >> 5;
        if (blk < 120) {
            int b = blk & 3, si = (blk >> 2) % 5, pc = blk / 20;
            int e = pc / 3, k = pc % 3;
            int pi = (k == 0) ? 0 : (e * 2 + k);
            int vid = c_VEC_ID[si][pi];
            const float* Dp = vid ? &g_D[vid][b][0] : (x + (size_t)b * N_NODES * 64);
            const float* Wp = W1 + (size_t)pc * 64 * 128;
            if (w < 12) {
                float4 acc = z4;
                for (int f = w; f < 64; f += 12) {
                    float d = vid ? ldcg1(Dp + f) : __ldg(Dp + f);
                    float4 wv = __ldg((const float4*)(Wp + (size_t)f * 128) + lane);
                    acc.x += d * wv.x; acc.y += d * wv.y;
                    acc.z += d * wv.z; acc.w += d * wv.w;
                }
                part[w][lane] = acc;
            }
            __syncthreads();
            if (w == 0) {
                float4 o = z4;
#pragma unroll
                for (int i = 0; i < 12; i++) {
                    float4 a = part[i][lane];
                    o.x += a.x; o.y += a.y; o.z += a.z; o.w += a.w;
                }
                float* tp = &g_T[si][b][lane * 4];
                atomicAdd(tp + 0, o.x); atomicAdd(tp + 1, o.y);
                atomicAdd(tp + 2, o.z); atomicAdd(tp + 3, o.w);
            }
        } else {
            int b = blk - 120;
            if (tid < 32)
                ((float4*)(out + (size_t)b * 128))[tid] = __ldg((const float4*)b2 + tid);
        }
    }
    if (blk >= 24) { barrier_arrive(124); return; }
    barrier_wait(124);

    // ---- P6b: blocks 0..23 out partials; spare warps zero D ----
    {
        int b = blk & 3, pc = blk >> 2;
        int e = pc / 3, k = pc % 3;
        int si = (k == 0) ? 0 : (e * 2 + k);
        float sg = (si == 0) ? 1.0f : ldcg1(&g_sig[si]);
        int lane = tid & 31, w = tid >> 5;
        const float* Tp = &g_T[si][b][0];
        const float* Wp = W2 + (size_t)pc * 128 * 128;
        if (w < 12) {
            float4 acc = z4;
            for (int f = w; f < 128; f += 12) {
                float t = ldcg1(Tp + f) + sg * __ldg(b1 + f);
                float4 wv = __ldg((const float4*)(Wp + (size_t)f * 128) + lane);
                acc.x += t * wv.x; acc.y += t * wv.y;
                acc.z += t * wv.z; acc.w += t * wv.w;
            }
            part[w][lane] = acc;
        } else {
            // zero D (not read in P6b): 24 blocks x 640 threads cover 4352 floats
            for (int i = blk * 640 + (tid - 384); i < 17 * 4 * 64; i += 24 * 640)
                (&g_D[0][0][0])[i] = 0.f;
        }
        __syncthreads();
        if (w == 0) {
            float4 o = z4;
#pragma unroll
            for (int i = 0; i < 12; i++) {
                float4 a = part[i][lane];
                o.x += a.x; o.y += a.y; o.z += a.z; o.w += a.w;
            }
            float* op = out + (size_t)b * 128 + lane * 4;
            atomicAdd(op + 0, o.x); atomicAdd(op + 1, o.y);
            atomicAdd(op + 2, o.z); atomicAdd(op + 3, o.w);
        }
    }
    barrier_wait(24);
    // zero T and sig (read in P6b, safe only after the 24-block barrier)
    for (int i = blk * NT + tid; i < 5 * 4 * 128; i += 24 * NT) (&g_T[0][0][0])[i] = 0.f;
    if (blk == 0 && tid < 5) g_sig[tid] = 0.f;
}

extern "C" void kernel_launch(void* const* d_in, const int* in_sizes, int n_in,
                              void* d_out, int out_size) {
    const float* x = nullptr;
    const int* eidx = nullptr;
    const float* evals = nullptr;
    const float *W1 = nullptr, *b1 = nullptr, *W2 = nullptr, *b2 = nullptr;
    for (int i = 0; i < n_in; i++) {
        switch (in_sizes[i]) {
            case 2560000: x = (const float*)d_in[i]; break;
            case 1280000: eidx = (const int*)d_in[i]; break;
            case 640000:  evals = (const float*)d_in[i]; break;
            case 49152:   W1 = (const float*)d_in[i]; break;
            case 98304:   W2 = (const float*)d_in[i]; break;
            case 128:
                if (!b1) b1 = (const float*)d_in[i];
                else b2 = (const float*)d_in[i];
                break;
        }
    }
    float* out = (float*)d_out;
    fused_kernel<<<NB, NT>>>(eidx, evals, x, W1, b1, W2, b2, out);
}

// round 8
// speedup vs baseline: 1.1619x; 1.1619x over previous
#include <cuda_runtime.h>

#define N_NODES 10000
#define N_EDGES 320000
#define QUADS (N_EDGES / 4)
#define NB 148
#define NT 1024
#define NTHR (NB * NT)
#define BM_WORDS 320
#define DC 68   // dot chunk: 148 blocks x 68 >= 10000

// Packed probe-vector storage. INVARIANT: all __device__ scratch is ZERO at
// kernel entry and restored to ZERO before exit (module load guarantees the
// first call; each call re-zeroes after last use). All intra-launch reads of
// atomically-written arrays happen strictly after their producer phase and
// each array is never regular-loaded earlier in the launch, so L1-cached
// __ldg is safe (L1 is flushed at launch boundaries on sm_103a).
__device__ float2 g_CL1[N_NODES];   // {R1, R2}
__device__ float4 g_CL2[N_NODES];   // {R3, R5, R4, R6}
__device__ float4 g_CL3a[N_NODES];  // {R7, R10, R11, pad}
__device__ float4 g_CL3b[N_NODES];  // {R8, R9, R12, pad}
__device__ float4 g_CL4[N_NODES];   // {R13, R15, R14, R16}
__device__ unsigned g_bm1[BM_WORDS];
__device__ unsigned g_bm2[BM_WORDS];
__device__ float g_D[17][4][64];
__device__ float g_T[5][4][128];
__device__ float g_sig[5];
__device__ int g_count;             // returns to 0 at each barrier
__device__ volatile int g_gen;      // monotonic; equality-compare only

__constant__ int c_VEC_ID[5][5] = {
    {0, 1, 3, 2, 6},
    {1, 3, 7, 4, 9},
    {3, 7, 13, 8, 14},
    {2, 5, 10, 6, 12},
    {6, 11, 15, 12, 16}};
__constant__ int c_SVID[16] = {1, 2, 3, 5, 4, 6, 7, 10, 11, 8, 9, 12, 13, 15, 14, 16};

__device__ __forceinline__ void red2(float* p, float a, float b) {
    asm volatile("red.global.add.v2.f32 [%0], {%1,%2};" :: "l"(p), "f"(a), "f"(b) : "memory");
}
__device__ __forceinline__ void red4(float* p, float a, float b, float c, float d) {
    asm volatile("red.global.add.v4.f32 [%0], {%1,%2,%3,%4};"
                 :: "l"(p), "f"(a), "f"(b), "f"(c), "f"(d) : "memory");
}

__device__ __forceinline__ void barrier_arrive(int target) {
    __syncthreads();
    if (threadIdx.x == 0) {
        __threadfence();
        int gen = g_gen;
        if (atomicAdd(&g_count, 1) == target - 1) {
            g_count = 0;
            __threadfence();
            g_gen = gen + 1;
        }
    }
}
__device__ __forceinline__ void barrier_wait(int target) {
    __syncthreads();
    if (threadIdx.x == 0) {
        __threadfence();
        int gen = g_gen;
        if (atomicAdd(&g_count, 1) == target - 1) {
            g_count = 0;
            __threadfence();
            g_gen = gen + 1;
        } else {
            while (g_gen == gen) __nanosleep(64);
        }
    }
    __syncthreads();
}

__global__ void __launch_bounds__(NT, 1)
fused_kernel(const int* __restrict__ eidx, const float* __restrict__ evals,
             const float* __restrict__ x,
             const float* __restrict__ W1, const float* __restrict__ b1,
             const float* __restrict__ W2, const float* __restrict__ b2,
             float* __restrict__ out) {
    __shared__ __align__(16) float pool[1920];  // Rs (dot) / part (epilogue)
    __shared__ unsigned sbm[BM_WORDS];
    float4 (*part)[32] = reinterpret_cast<float4(*)[32]>(pool);

    const int tid = threadIdx.x;
    const int blk = blockIdx.x;
    const int gtid = blk * NT + tid;
    const float4 z4 = make_float4(0.f, 0.f, 0.f, 0.f);

    // ---- P1: lvl1 (parent = e_0, no gather) + build bm1 ----
    for (int q = gtid; q < 2 * QUADS; q += NTHR) {
        int g = q >= QUADS;
        int j = q - g * QUADS;
        const int* eb = eidx + (size_t)g * 2 * N_EDGES;
        int4 r = __ldg((const int4*)eb + j);
        if (r.x == 0 || r.y == 0 || r.z == 0 || r.w == 0) {
            const int ri[4] = {r.x, r.y, r.z, r.w};
            float* base = (float*)g_CL1 + g;
#pragma unroll
            for (int i = 0; i < 4; i++)
                if (ri[i] == 0) {
                    int c = __ldg(eb + N_EDGES + j * 4 + i);
                    float v = __ldg(evals + (size_t)g * N_EDGES + j * 4 + i);
                    atomicAdd(base + c * 2, v);
                    atomicOr(&g_bm1[c >> 5], 1u << (c & 31));
                }
        }
    }
    barrier_wait(NB);

    // ---- P2: lvl2 (bm1-filtered, L1 gathers) + build bm2 ----
    if (tid < BM_WORDS) sbm[tid] = __ldg(&g_bm1[tid]);
    __syncthreads();
    for (int q = gtid; q < 2 * QUADS; q += NTHR) {
        int g = q >= QUADS;
        int j = q - g * QUADS;
        const int* eb = eidx + (size_t)g * 2 * N_EDGES;
        int4 r = __ldg((const int4*)eb + j);
        const int ri[4] = {r.x, r.y, r.z, r.w};
        unsigned any = 0;
#pragma unroll
        for (int i = 0; i < 4; i++)
            any |= (sbm[ri[i] >> 5] >> (ri[i] & 31)) & 1u ? (1u << i) : 0u;
        if (!any) continue;
        float* base = (float*)g_CL2 + 2 * g;
#pragma unroll
        for (int i = 0; i < 4; i++)
            if (any & (1u << i)) {
                float2 qv = __ldg(g_CL1 + ri[i]);
                if ((qv.x != 0.f) | (qv.y != 0.f)) {
                    int c = __ldg(eb + N_EDGES + j * 4 + i);
                    float v = __ldg(evals + (size_t)g * N_EDGES + j * 4 + i);
                    red2(base + c * 4, v * qv.x, v * qv.y);
                    atomicOr(&g_bm2[c >> 5], 1u << (c & 31));
                }
            }
    }
    barrier_wait(NB);

    // ---- P3: lvl3 (bm2-filtered, L1 gathers) ----
    if (tid < BM_WORDS) sbm[tid] = __ldg(&g_bm2[tid]);
    __syncthreads();
    for (int q = gtid; q < 2 * QUADS; q += NTHR) {
        int g = q >= QUADS;
        int j = q - g * QUADS;
        const int* eb = eidx + (size_t)g * 2 * N_EDGES;
        int4 r = __ldg((const int4*)eb + j);
        const int ri[4] = {r.x, r.y, r.z, r.w};
        unsigned any = 0;
#pragma unroll
        for (int i = 0; i < 4; i++)
            any |= (sbm[ri[i] >> 5] >> (ri[i] & 31)) & 1u ? (1u << i) : 0u;
        if (!any) continue;
        float4* dst = g ? g_CL3b : g_CL3a;
#pragma unroll
        for (int i = 0; i < 4; i++)
            if (any & (1u << i)) {
                float4 qv = __ldg(g_CL2 + ri[i]);
                float p0 = qv.x;
                float p1 = g ? qv.z : qv.y;
                float p2 = qv.w;
                if ((p0 != 0.f) | (p1 != 0.f) | (p2 != 0.f)) {
                    int c = __ldg(eb + N_EDGES + j * 4 + i);
                    float v = __ldg(evals + (size_t)g * N_EDGES + j * 4 + i);
                    red4((float*)&dst[c], v * p0, v * p1, v * p2, 0.f);
                }
            }
    }
    barrier_wait(NB);

    // ---- P4: lvl4 (dense, L1 gathers; 2+2 gather pipeline) ----
    for (int q = gtid; q < 2 * QUADS; q += NTHR) {
        int g = q >= QUADS;
        int j = q - g * QUADS;
        const int* eb = eidx + (size_t)g * 2 * N_EDGES;
        const float4* src = g ? g_CL3b : g_CL3a;
        int4 r = __ldg((const int4*)eb + j);
        int4 c = __ldg((const int4*)(eb + N_EDGES) + j);
        float4 v = __ldg((const float4*)(evals + (size_t)g * N_EDGES) + j);
        float* base = (float*)g_CL4 + 2 * g;
        {
            float4 q0 = __ldg(src + r.x), q1 = __ldg(src + r.y);
            if ((q0.x != 0.f) | (q0.z != 0.f)) red2(base + c.x * 4, v.x * q0.x, v.x * q0.z);
            if ((q1.x != 0.f) | (q1.z != 0.f)) red2(base + c.y * 4, v.y * q1.x, v.y * q1.z);
        }
        {
            float4 q2 = __ldg(src + r.z), q3 = __ldg(src + r.w);
            if ((q2.x != 0.f) | (q2.z != 0.f)) red2(base + c.z * 4, v.z * q2.x, v.z * q2.z);
            if ((q3.x != 0.f) | (q3.z != 0.f)) red2(base + c.w * 4, v.w * q3.x, v.w * q3.z);
        }
    }
    barrier_wait(NB);

    // ---- P5: dot (all 16 slots) + sigma + zero CL arrays and bitmaps ----
    {
        int n0 = blk * DC;
        int lim = min(DC, N_NODES - n0);
        if (tid < lim) {
            int gn = n0 + tid;
            float2 a = __ldg(g_CL1 + gn);
            float4 c2 = __ldg(g_CL2 + gn);
            float4 c3a = __ldg(g_CL3a + gn);
            float4 c3b = __ldg(g_CL3b + gn);
            float4 c4 = __ldg(g_CL4 + gn);
            pool[0 * DC + tid] = a.x;   pool[1 * DC + tid] = a.y;
            pool[2 * DC + tid] = c2.x;  pool[3 * DC + tid] = c2.y;
            pool[4 * DC + tid] = c2.z;  pool[5 * DC + tid] = c2.w;
            pool[6 * DC + tid] = c3a.x; pool[7 * DC + tid] = c3a.y;
            pool[8 * DC + tid] = c3a.z;
            pool[9 * DC + tid] = c3b.x; pool[10 * DC + tid] = c3b.y;
            pool[11 * DC + tid] = c3b.z;
            pool[12 * DC + tid] = c4.x; pool[13 * DC + tid] = c4.y;
            pool[14 * DC + tid] = c4.z; pool[15 * DC + tid] = c4.w;
            // restore zeros (after the loads; same thread = program order)
            g_CL1[gn] = make_float2(0.f, 0.f);
            g_CL2[gn] = z4; g_CL3a[gn] = z4; g_CL3b[gn] = z4; g_CL4[gn] = z4;
        }
        if (blk == 0 && tid >= 512 && tid < 512 + BM_WORDS) {
            g_bm1[tid - 512] = 0u;
            g_bm2[tid - 512] = 0u;
        }
        __syncthreads();
        if (tid < 128) {  // sigma: sig[1..4] = column sums of slots {0,2,1,5}
            const int slots[4] = {0, 2, 1, 5};
            int vi = tid >> 5, lane = tid & 31;
            float s = 0.f;
            for (int n = lane; n < lim; n += 32) s += pool[slots[vi] * DC + n];
#pragma unroll
            for (int off = 16; off; off >>= 1) s += __shfl_down_sync(0xffffffffu, s, off);
            if (lane == 0) atomicAdd(&g_sig[vi + 1], s);
        }
        int f = tid & 63;
        int bb = (tid >> 6) & 3;
        int vg = tid >> 8;
        float acc0 = 0.f, acc1 = 0.f, acc2 = 0.f, acc3 = 0.f;
        const float* xb = x + ((size_t)bb * N_NODES + n0) * 64 + f;
        const float* rsv = pool + vg * 4 * DC;
        for (int nn = 0; nn < lim; nn++) {
            float xv = __ldg(xb + (size_t)nn * 64);
            acc0 += rsv[0 * DC + nn] * xv;
            acc1 += rsv[1 * DC + nn] * xv;
            acc2 += rsv[2 * DC + nn] * xv;
            acc3 += rsv[3 * DC + nn] * xv;
        }
        atomicAdd(&g_D[c_SVID[vg * 4 + 0]][bb][f], acc0);
        atomicAdd(&g_D[c_SVID[vg * 4 + 1]][bb][f], acc1);
        atomicAdd(&g_D[c_SVID[vg * 4 + 2]][bb][f], acc2);
        atomicAdd(&g_D[c_SVID[vg * 4 + 3]][bb][f], acc3);
    }
    if (blk >= 124) { barrier_arrive(NB); return; }
    barrier_wait(NB);

    // ---- P6a: blocks 0..119 T partials; 120..123 init out = b2 ----
    {
        int lane = tid & 31, w = tid >> 5;
        if (blk < 120) {
            int b = blk & 3, si = (blk >> 2) % 5, pc = blk / 20;
            int e = pc / 3, k = pc % 3;
            int pi = (k == 0) ? 0 : (e * 2 + k);
            int vid = c_VEC_ID[si][pi];
            const float* Dp = vid ? &g_D[vid][b][0] : (x + (size_t)b * N_NODES * 64);
            const float* Wp = W1 + (size_t)pc * 64 * 128;
            if (w < 12) {
                float4 acc = z4;
                for (int f = w; f < 64; f += 12) {
                    float d = __ldg(Dp + f);
                    float4 wv = __ldg((const float4*)(Wp + (size_t)f * 128) + lane);
                    acc.x += d * wv.x; acc.y += d * wv.y;
                    acc.z += d * wv.z; acc.w += d * wv.w;
                }
                part[w][lane] = acc;
            }
            __syncthreads();
            if (w == 0) {
                float4 o = z4;
#pragma unroll
                for (int i = 0; i < 12; i++) {
                    float4 a = part[i][lane];
                    o.x += a.x; o.y += a.y; o.z += a.z; o.w += a.w;
                }
                float* tp = &g_T[si][b][lane * 4];
                atomicAdd(tp + 0, o.x); atomicAdd(tp + 1, o.y);
                atomicAdd(tp + 2, o.z); atomicAdd(tp + 3, o.w);
            }
        } else {
            int b = blk - 120;
            if (tid < 32)
                ((float4*)(out + (size_t)b * 128))[tid] = __ldg((const float4*)b2 + tid);
        }
    }
    if (blk >= 24) { barrier_arrive(124); return; }
    barrier_wait(124);

    // ---- P6b: blocks 0..23 out partials; spare warps zero D ----
    {
        int b = blk & 3, pc = blk >> 2;
        int e = pc / 3, k = pc % 3;
        int si = (k == 0) ? 0 : (e * 2 + k);
        float sg = (si == 0) ? 1.0f : __ldg(&g_sig[si]);
        int lane = tid & 31, w = tid >> 5;
        const float* Tp = &g_T[si][b][0];
        const float* Wp = W2 + (size_t)pc * 128 * 128;
        if (w < 12) {
            float4 acc = z4;
            for (int f = w; f < 128; f += 12) {
                float t = __ldg(Tp + f) + sg * __ldg(b1 + f);
                float4 wv = __ldg((const float4*)(Wp + (size_t)f * 128) + lane);
                acc.x += t * wv.x; acc.y += t * wv.y;
                acc.z += t * wv.z; acc.w += t * wv.w;
            }
            part[w][lane] = acc;
        } else {
            // zero D (not read in P6b): blocks 0..23 x 640 threads cover 4352
            for (int i = blk * 640 + (tid - 384); i < 17 * 4 * 64; i += 24 * 640)
                (&g_D[0][0][0])[i] = 0.f;
        }
        __syncthreads();
        if (w == 0) {
            float4 o = z4;
#pragma unroll
            for (int i = 0; i < 12; i++) {
                float4 a = part[i][lane];
                o.x += a.x; o.y += a.y; o.z += a.z; o.w += a.w;
            }
            float* op = out + (size_t)b * 128 + lane * 4;
            atomicAdd(op + 0, o.x); atomicAdd(op + 1, o.y);
            atomicAdd(op + 2, o.z); atomicAdd(op + 3, o.w);
        }
    }
    barrier_wait(24);
    // zero T and sig (read in P6b, safe only after the 24-block barrier)
    for (int i = blk * NT + tid; i < 5 * 4 * 128; i += 24 * NT) (&g_T[0][0][0])[i] = 0.f;
    if (blk == 0 && tid < 5) g_sig[tid] = 0.f;
}

extern "C" void kernel_launch(void* const* d_in, const int* in_sizes, int n_in,
                              void* d_out, int out_size) {
    const float* x = nullptr;
    const int* eidx = nullptr;
    const float* evals = nullptr;
    const float *W1 = nullptr, *b1 = nullptr, *W2 = nullptr, *b2 = nullptr;
    for (int i = 0; i < n_in; i++) {
        switch (in_sizes[i]) {
            case 2560000: x = (const float*)d_in[i]; break;
            case 1280000: eidx = (const int*)d_in[i]; break;
            case 640000:  evals = (const float*)d_in[i]; break;
            case 49152:   W1 = (const float*)d_in[i]; break;
            case 98304:   W2 = (const float*)d_in[i]; break;
            case 128:
                if (!b1) b1 = (const float*)d_in[i];
                else b2 = (const float*)d_in[i];
                break;
        }
    }
    float* out = (float*)d_out;
    fused_kernel<<<NB, NT>>>(eidx, evals, x, W1, b1, W2, b2, out);
}